// round 8
// baseline (speedup 1.0000x reference)
#include <cuda_runtime.h>
#include <math.h>

#define IMG    512
#define IMG2   (IMG * IMG)        // 262144 elements per image
#define NBATCH 16
#define NTEN   (NBATCH * IMG2)    // 4194304 per tensor
#define NTOT   (2 * NTEN)         // 8388608 both tensors
#define BMP_WORDS 131080          // ceil((NTEN+1)/32) = 131073, padded
#define FULLMASK 0xffffffffu
#define BIGF 3.0e38f              // 1*BIGF finite (<FLT_MAX) and > any label

// ---------------- device scratch (static, no allocation) ----------------
__device__ float    g_buf[2][NTOT];       // ping-pong label buffers (pred | target)
__device__ unsigned g_bmp[2][BMP_WORDS];  // uniqueness bitmaps
__device__ float    g_pnum[512];          // per (batch,chunk) partial sum p*t
__device__ float    g_pden[512];          // per (batch,chunk) partial sum p^2+t^2
__device__ int      g_maxbits[2];         // float-as-int global max of p, t (values >= 0)
__device__ int      g_cnt[2];             // unique counts

// ---------------- helpers ----------------
__device__ __forceinline__ float4 fmax4(float4 a, float4 b) {
    return make_float4(fmaxf(a.x, b.x), fmaxf(a.y, b.y),
                       fmaxf(a.z, b.z), fmaxf(a.w, b.w));
}

// ---------------- init: clear scratch ----------------
__global__ void init_kernel() {
    int i = blockIdx.x * blockDim.x + threadIdx.x;
    int stride = gridDim.x * blockDim.x;
    for (int w = i; w < BMP_WORDS; w += stride) {
        g_bmp[0][w] = 0u;
        g_bmp[1][w] = 0u;
    }
    if (i < 512) { g_pnum[i] = 0.f; g_pden[i] = 0.f; }
    if (i < 2)   { g_maxbits[i] = 0; g_cnt[i] = 0; }
}

// ---------------- pass 1: dice partial sums + global maxes ----------------
__global__ void __launch_bounds__(256) reduce_kernel(const float* __restrict__ p,
                                                     const float* __restrict__ t) {
    const int b = blockIdx.y, c = blockIdx.x, tid = threadIdx.x;
    const float4* p4 = reinterpret_cast<const float4*>(p + (size_t)b * IMG2) + c * 2048;
    const float4* t4 = reinterpret_cast<const float4*>(t + (size_t)b * IMG2) + c * 2048;
    float s1 = 0.f, s2 = 0.f, mp = 0.f, mt = 0.f;
#pragma unroll
    for (int k = 0; k < 8; k++) {
        float4 a = p4[k * 256 + tid];
        float4 d = t4[k * 256 + tid];
        s1 += a.x * d.x + a.y * d.y + a.z * d.z + a.w * d.w;
        s2 += a.x * a.x + a.y * a.y + a.z * a.z + a.w * a.w;
        s2 += d.x * d.x + d.y * d.y + d.z * d.z + d.w * d.w;
        mp = fmaxf(mp, fmaxf(fmaxf(a.x, a.y), fmaxf(a.z, a.w)));
        mt = fmaxf(mt, fmaxf(fmaxf(d.x, d.y), fmaxf(d.z, d.w)));
    }
#pragma unroll
    for (int o = 16; o; o >>= 1) {
        s1 += __shfl_down_sync(FULLMASK, s1, o);
        s2 += __shfl_down_sync(FULLMASK, s2, o);
        mp = fmaxf(mp, __shfl_down_sync(FULLMASK, mp, o));
        mt = fmaxf(mt, __shfl_down_sync(FULLMASK, mt, o));
    }
    __shared__ float sh1[8], sh2[8], shm[8], sht[8];
    if ((tid & 31) == 0) {
        int w = tid >> 5;
        sh1[w] = s1; sh2[w] = s2; shm[w] = mp; sht[w] = mt;
    }
    __syncthreads();
    if (tid == 0) {
        float a1 = sh1[0], a2 = sh2[0], m1 = shm[0], m2 = sht[0];
        for (int w = 1; w < 8; w++) {
            a1 += sh1[w]; a2 += sh2[w];
            m1 = fmaxf(m1, shm[w]); m2 = fmaxf(m2, sht[w]);
        }
        g_pnum[b * 32 + c] = a1;
        g_pden[b * 32 + c] = a2;
        atomicMax(&g_maxbits[0], __float_as_int(m1));  // vals >= 0: int order == float order
        atomicMax(&g_maxbits[1], __float_as_int(m2));
    }
}

// ---------------- pass 2: build seed arrays ----------------
__global__ void __launch_bounds__(256) seed_kernel(const float* __restrict__ p,
                                                   const float* __restrict__ t) {
    int i = blockIdx.x * blockDim.x + threadIdx.x;   // float4 index, < NTEN/4
    float thp = 0.5f * __int_as_float(g_maxbits[0]);
    float tht = 0.5f * __int_as_float(g_maxbits[1]);
    int base = 4 * i;
    float4 a = reinterpret_cast<const float4*>(p)[i];
    float4 s;
    s.x = (a.x > thp) ? (float)(base + 1) : 0.f;
    s.y = (a.y > thp) ? (float)(base + 2) : 0.f;
    s.z = (a.z > thp) ? (float)(base + 3) : 0.f;
    s.w = (a.w > thp) ? (float)(base + 4) : 0.f;
    reinterpret_cast<float4*>(g_buf[0])[i] = s;
    float4 d = reinterpret_cast<const float4*>(t)[i];
    s.x = (d.x > tht) ? (float)(base + 1) : 0.f;
    s.y = (d.y > tht) ? (float)(base + 2) : 0.f;
    s.z = (d.z > tht) ? (float)(base + 3) : 0.f;
    s.w = (d.w > tht) ? (float)(base + 4) : 0.f;
    reinterpret_cast<float4*>(g_buf[0] + NTEN)[i] = s;
}

// ---------------- fused propagation: 8 masked 3x3 max-pool iterations ----------------
// Register-resident tile 128x64; valid output = tile minus margin 8 on
// image-interior sides. Warp w (0..15) owns rows 4w..4w+3; lane l owns cols
// 4l..4l+3 (float4). NO mask registers: masking via new = fmin(h, a_old*BIG)
// (exact: a>=1 -> a*BIG >= 3e38 > any label; a=0 -> 0). Vertical halo via
// static smem with ZEROED GUARD SLOTS (no selects), parity double-buffered,
// one __syncthreads per iteration. __launch_bounds__(512,3): <=42 regs so
// 3 blocks (48 warps) co-reside per SM.
__device__ __forceinline__ float4 hmin(const float4 v, const float4 a,
                                       float eL, float eR) {
    float vl = __shfl_up_sync(FULLMASK,  v.w, 1) * eL;
    float vr = __shfl_down_sync(FULLMASK, v.x, 1) * eR;
    float mxy = fmaxf(v.x, v.y);
    float mzw = fmaxf(v.z, v.w);
    float4 o;
    o.x = fminf(fmaxf(vl,  mxy), a.x * BIGF);
    o.y = fminf(fmaxf(mxy, v.z), a.y * BIGF);
    o.z = fminf(fmaxf(v.y, mzw), a.z * BIGF);
    o.w = fminf(fmaxf(mzw, vr),  a.w * BIGF);
    return o;
}

__global__ void __launch_bounds__(512, 3) prop8_kernel(int src) {
    const float* __restrict__ in  = g_buf[src];
    float*       __restrict__ out = g_buf[src ^ 1];
    const int img = blockIdx.z;
    const int X0 = min((int)blockIdx.x * 112, 384);   // {0,112,224,336,384}
    const int Y0 = min((int)blockIdx.y * 48,  448);   // {0,48,...,432,448}
    const int w = threadIdx.x >> 5, l = threadIdx.x & 31;
    const int gx  = X0 + 4 * l;
    const int gy0 = Y0 + 4 * w;
    const float* base = in + (size_t)img * IMG2;

    float4 a0 = *reinterpret_cast<const float4*>(base + (gy0 + 0) * IMG + gx);
    float4 a1 = *reinterpret_cast<const float4*>(base + (gy0 + 1) * IMG + gx);
    float4 a2 = *reinterpret_cast<const float4*>(base + (gy0 + 2) * IMG + gx);
    float4 a3 = *reinterpret_cast<const float4*>(base + (gy0 + 3) * IMG + gx);

    const float eL = (l == 0)  ? 0.f : 1.f;   // tile x-edge clamp
    const float eR = (l == 31) ? 0.f : 1.f;

    // guard-slot halo buffers:
    //   shTop: warp w writes slot w,   reads slot w+1 (zero guard @16)
    //   shBot: warp w writes slot w+1, reads slot w   (zero guard @0)
    __shared__ float4 shTop[2][17][32];
    __shared__ float4 shBot[2][17][32];
    if (threadIdx.x < 32) {
        const float4 z4 = make_float4(0.f, 0.f, 0.f, 0.f);
        shTop[0][16][l] = z4;  shTop[1][16][l] = z4;
        shBot[0][0][l]  = z4;  shBot[1][0][l]  = z4;
    }

#pragma unroll
    for (int i = 0; i < 8; i++) {
        const int p = i & 1;
        shTop[p][w][l]     = a0;
        shBot[p][w + 1][l] = a3;
        __syncthreads();
        float4 aT = shBot[p][w][l];       // w=0  -> zero guard
        float4 aB = shTop[p][w + 1][l];   // w=15 -> zero guard
        // vertical 3-max with minimal CSE (c01, c23 only)
        float4 c01 = fmax4(a0, a1);
        float4 c23 = fmax4(a2, a3);
        float4 v0 = fmax4(aT,  c01);
        float4 v1 = fmax4(c01, a2);
        float4 v2 = fmax4(a1,  c23);
        float4 v3 = fmax4(c23, aB);
        a0 = hmin(v0, a0, eL, eR);
        a1 = hmin(v1, a1, eL, eR);
        a2 = hmin(v2, a2, eL, eR);
        a3 = hmin(v3, a3, eL, eR);
    }

    // store valid (margin-8 or image-edge) region; overlap writes are identical
    const int vx0 = (X0 == 0)   ? 0   : X0 + 8;
    const int vx1 = (X0 == 384) ? 512 : X0 + 120;
    const int vy0 = (Y0 == 0)   ? 0   : Y0 + 8;
    const int vy1 = (Y0 == 448) ? 512 : Y0 + 56;
    float* obase = out + (size_t)img * IMG2;
    if (gx >= vx0 && gx < vx1) {
        if (gy0 + 0 >= vy0 && gy0 + 0 < vy1)
            *reinterpret_cast<float4*>(obase + (gy0 + 0) * IMG + gx) = a0;
        if (gy0 + 1 >= vy0 && gy0 + 1 < vy1)
            *reinterpret_cast<float4*>(obase + (gy0 + 1) * IMG + gx) = a1;
        if (gy0 + 2 >= vy0 && gy0 + 2 < vy1)
            *reinterpret_cast<float4*>(obase + (gy0 + 2) * IMG + gx) = a2;
        if (gy0 + 3 >= vy0 && gy0 + 3 < vy1)
            *reinterpret_cast<float4*>(obase + (gy0 + 3) * IMG + gx) = a3;
    }
}

// ---------------- uniqueness: bitmap scatter (reads g_buf[1]) ----------------
__global__ void __launch_bounds__(256) scatter_kernel() {
    int i = blockIdx.x * blockDim.x + threadIdx.x;   // float4 index, < NTOT/4
    float4 v = reinterpret_cast<const float4*>(g_buf[1])[i];
    unsigned* bmp = (i < (NTEN / 4)) ? g_bmp[0] : g_bmp[1];
    unsigned ids[4] = {(unsigned)v.x, (unsigned)v.y, (unsigned)v.z, (unsigned)v.w};
    unsigned prev = 0xffffffffu;
#pragma unroll
    for (int k = 0; k < 4; k++) {
        unsigned id = ids[k];
        if (id == prev) continue;                 // spatial dedup (labels cluster)
        prev = id;
        unsigned w = id >> 5, m = 1u << (id & 31);
        if (!(bmp[w] & m)) atomicOr(&bmp[w], m);  // test first: idempotent
    }
}

__global__ void __launch_bounds__(256) popcnt_kernel() {
    int which = blockIdx.y;
    int i = blockIdx.x * blockDim.x + threadIdx.x;
    int stride = gridDim.x * blockDim.x;
    int s = 0;
    for (int w = i; w < BMP_WORDS; w += stride) s += __popc(g_bmp[which][w]);
#pragma unroll
    for (int o = 16; o; o >>= 1) s += __shfl_down_sync(FULLMASK, s, o);
    __shared__ int sh[8];
    if ((threadIdx.x & 31) == 0) sh[threadIdx.x >> 5] = s;
    __syncthreads();
    if (threadIdx.x == 0) {
        int tot = 0;
        for (int w = 0; w < 8; w++) tot += sh[w];
        atomicAdd(&g_cnt[which], tot);
    }
}

// ---------------- epilogue ----------------
__global__ void final_kernel(float* __restrict__ out) {
    float acc = 0.f;
    for (int b = 0; b < NBATCH; b++) {
        float num = 0.f, den = 0.f;
        for (int c = 0; c < 32; c++) { num += g_pnum[b * 32 + c]; den += g_pden[b * 32 + c]; }
        acc += 1.0f - (num + 1.0f) / (den + 1.0f);
    }
    float nl = (float)(g_cnt[0] - 1);   // count_unique(labels) - 1
    float nt = (float)g_cnt[1];         // count_unique(target_number)
    float pen = sqrtf(nl / nt);
    if (!isfinite(pen)) pen = (float)NBATCH;
    pen = fminf(fmaxf(pen, 1.0f), (float)NBATCH);
    out[0] = (acc / (float)NBATCH) * pen;
}

// ---------------- launch ----------------
extern "C" void kernel_launch(void* const* d_in, const int* in_sizes, int n_in,
                              void* d_out, int out_size) {
    const float* p = (const float*)d_in[0];
    const float* t = (const float*)d_in[1];
    float* out = (float*)d_out;

    init_kernel<<<512, 256>>>();

    dim3 rgrid(32, 16);
    reduce_kernel<<<rgrid, 256>>>(p, t);

    seed_kernel<<<NTEN / 4 / 256, 256>>>(p, t);

    // 25 launches x 8 fused iterations = 200; ping-pong g_buf[0] <-> g_buf[1]
    dim3 pgrid(5, 11, 32);
    for (int it = 0; it < 25; ++it)
        prop8_kernel<<<pgrid, 512>>>(it & 1);     // final result lands in g_buf[1]

    scatter_kernel<<<NTOT / 4 / 256, 256>>>();

    dim3 cgrid(64, 2);
    popcnt_kernel<<<cgrid, 256>>>();

    final_kernel<<<1, 1>>>(out);
}

// round 9
// speedup vs baseline: 1.0599x; 1.0599x over previous
#include <cuda_runtime.h>
#include <math.h>

#define IMG    512
#define IMG2   (IMG * IMG)        // 262144 elements per image
#define NBATCH 16
#define NTEN   (NBATCH * IMG2)    // 4194304 per tensor
#define NTOT   (2 * NTEN)         // 8388608 both tensors
#define BMP_WORDS 131080          // ceil((NTEN+1)/32) = 131073, padded
#define FULLMASK 0xffffffffu

// ---------------- device scratch (static, no allocation) ----------------
__device__ float    g_buf[2][NTOT];       // ping-pong label buffers (pred | target)
__device__ unsigned g_bmp[2][BMP_WORDS];  // uniqueness bitmaps
__device__ float    g_pnum[512];          // per (batch,chunk) partial sum p*t
__device__ float    g_pden[512];          // per (batch,chunk) partial sum p^2+t^2
__device__ int      g_maxbits[2];         // float-as-int global max of p, t (values >= 0)
__device__ int      g_cnt[2];             // unique counts

// ---------------- helpers ----------------
__device__ __forceinline__ float4 fmax4(float4 a, float4 b) {
    return make_float4(fmaxf(a.x, b.x), fmaxf(a.y, b.y),
                       fmaxf(a.z, b.z), fmaxf(a.w, b.w));
}

// ---------------- init: clear scratch ----------------
__global__ void init_kernel() {
    int i = blockIdx.x * blockDim.x + threadIdx.x;
    int stride = gridDim.x * blockDim.x;
    for (int w = i; w < BMP_WORDS; w += stride) {
        g_bmp[0][w] = 0u;
        g_bmp[1][w] = 0u;
    }
    if (i < 512) { g_pnum[i] = 0.f; g_pden[i] = 0.f; }
    if (i < 2)   { g_maxbits[i] = 0; g_cnt[i] = 0; }
}

// ---------------- pass 1: dice partial sums + global maxes ----------------
__global__ void __launch_bounds__(256) reduce_kernel(const float* __restrict__ p,
                                                     const float* __restrict__ t) {
    const int b = blockIdx.y, c = blockIdx.x, tid = threadIdx.x;
    const float4* p4 = reinterpret_cast<const float4*>(p + (size_t)b * IMG2) + c * 2048;
    const float4* t4 = reinterpret_cast<const float4*>(t + (size_t)b * IMG2) + c * 2048;
    float s1 = 0.f, s2 = 0.f, mp = 0.f, mt = 0.f;
#pragma unroll
    for (int k = 0; k < 8; k++) {
        float4 a = p4[k * 256 + tid];
        float4 d = t4[k * 256 + tid];
        s1 += a.x * d.x + a.y * d.y + a.z * d.z + a.w * d.w;
        s2 += a.x * a.x + a.y * a.y + a.z * a.z + a.w * a.w;
        s2 += d.x * d.x + d.y * d.y + d.z * d.z + d.w * d.w;
        mp = fmaxf(mp, fmaxf(fmaxf(a.x, a.y), fmaxf(a.z, a.w)));
        mt = fmaxf(mt, fmaxf(fmaxf(d.x, d.y), fmaxf(d.z, d.w)));
    }
#pragma unroll
    for (int o = 16; o; o >>= 1) {
        s1 += __shfl_down_sync(FULLMASK, s1, o);
        s2 += __shfl_down_sync(FULLMASK, s2, o);
        mp = fmaxf(mp, __shfl_down_sync(FULLMASK, mp, o));
        mt = fmaxf(mt, __shfl_down_sync(FULLMASK, mt, o));
    }
    __shared__ float sh1[8], sh2[8], shm[8], sht[8];
    if ((tid & 31) == 0) {
        int w = tid >> 5;
        sh1[w] = s1; sh2[w] = s2; shm[w] = mp; sht[w] = mt;
    }
    __syncthreads();
    if (tid == 0) {
        float a1 = sh1[0], a2 = sh2[0], m1 = shm[0], m2 = sht[0];
        for (int w = 1; w < 8; w++) {
            a1 += sh1[w]; a2 += sh2[w];
            m1 = fmaxf(m1, shm[w]); m2 = fmaxf(m2, sht[w]);
        }
        g_pnum[b * 32 + c] = a1;
        g_pden[b * 32 + c] = a2;
        atomicMax(&g_maxbits[0], __float_as_int(m1));  // vals >= 0: int order == float order
        atomicMax(&g_maxbits[1], __float_as_int(m2));
    }
}

// ---------------- pass 2: build seed arrays ----------------
__global__ void __launch_bounds__(256) seed_kernel(const float* __restrict__ p,
                                                   const float* __restrict__ t) {
    int i = blockIdx.x * blockDim.x + threadIdx.x;   // float4 index, < NTEN/4
    float thp = 0.5f * __int_as_float(g_maxbits[0]);
    float tht = 0.5f * __int_as_float(g_maxbits[1]);
    int base = 4 * i;
    float4 a = reinterpret_cast<const float4*>(p)[i];
    float4 s;
    s.x = (a.x > thp) ? (float)(base + 1) : 0.f;
    s.y = (a.y > thp) ? (float)(base + 2) : 0.f;
    s.z = (a.z > thp) ? (float)(base + 3) : 0.f;
    s.w = (a.w > thp) ? (float)(base + 4) : 0.f;
    reinterpret_cast<float4*>(g_buf[0])[i] = s;
    float4 d = reinterpret_cast<const float4*>(t)[i];
    s.x = (d.x > tht) ? (float)(base + 1) : 0.f;
    s.y = (d.y > tht) ? (float)(base + 2) : 0.f;
    s.z = (d.z > tht) ? (float)(base + 3) : 0.f;
    s.w = (d.w > tht) ? (float)(base + 4) : 0.f;
    reinterpret_cast<float4*>(g_buf[0] + NTEN)[i] = s;
}

// ---------------- fused propagation: 8 masked 3x3 max-pool iterations ----------------
// Register-resident tile 128x96 (edge-clamped origins keep it in-image); valid
// output = tile minus margin 8 on image-interior sides.
// Warp w (0..15) owns rows 6w..6w+5; lane l owns cols 4l..4l+3 (float4).
// Invariant 0/1 mask regs applied via FMUL (FMA pipe); lane-edge clamps via
// FMUL by 0/1 consts. Vertical halo via smem, parity double-buffered, one
// __syncthreads/iter. Body ordered for ILP: LDS of aT/aB issued right after
// the barrier; the 4 middle rows (register-only) are computed while the loads
// are in flight; edge rows consume them last.
__device__ __forceinline__ float4 hmask(const float4 v, const float4 m,
                                        float eL, float eR) {
    float vl = __shfl_up_sync(FULLMASK,  v.w, 1) * eL;
    float vr = __shfl_down_sync(FULLMASK, v.x, 1) * eR;
    float mxy = fmaxf(v.x, v.y);
    float mzw = fmaxf(v.z, v.w);
    float4 o;
    o.x = fmaxf(vl,  mxy) * m.x;   // mask FMUL: exact for 0/1 masks, h >= 0
    o.y = fmaxf(mxy, v.z) * m.y;
    o.z = fmaxf(v.y, mzw) * m.z;
    o.w = fmaxf(mzw, vr)  * m.w;
    return o;
}
__device__ __forceinline__ float4 mk_mask(const float4 a) {
    return make_float4(a.x > 0.f ? 1.f : 0.f, a.y > 0.f ? 1.f : 0.f,
                       a.z > 0.f ? 1.f : 0.f, a.w > 0.f ? 1.f : 0.f);
}

__global__ void __launch_bounds__(512, 2) prop8_kernel(int src) {
    const float* __restrict__ in  = g_buf[src];
    float*       __restrict__ out = g_buf[src ^ 1];
    const int img = blockIdx.z;
    const int X0 = min((int)blockIdx.x * 112, 384);   // 5 x-tiles
    const int Y0 = min((int)blockIdx.y * 80,  416);   // 7 y-tiles {0,80,...,400,416}
    const int w = threadIdx.x >> 5, l = threadIdx.x & 31;
    const int gx  = X0 + 4 * l;
    const int gy0 = Y0 + 6 * w;
    const float* base = in + (size_t)img * IMG2;

    float4 a0 = *reinterpret_cast<const float4*>(base + (gy0 + 0) * IMG + gx);
    float4 a1 = *reinterpret_cast<const float4*>(base + (gy0 + 1) * IMG + gx);
    float4 a2 = *reinterpret_cast<const float4*>(base + (gy0 + 2) * IMG + gx);
    float4 a3 = *reinterpret_cast<const float4*>(base + (gy0 + 3) * IMG + gx);
    float4 a4 = *reinterpret_cast<const float4*>(base + (gy0 + 4) * IMG + gx);
    float4 a5 = *reinterpret_cast<const float4*>(base + (gy0 + 5) * IMG + gx);

    // invariant 0/1 mask registers (masked-out pixels stay 0 across all iters)
    float4 m0 = mk_mask(a0), m1 = mk_mask(a1), m2 = mk_mask(a2);
    float4 m3 = mk_mask(a3), m4 = mk_mask(a4), m5 = mk_mask(a5);

    const float eL = (l == 0)  ? 0.f : 1.f;   // tile x-edge clamp
    const float eR = (l == 31) ? 0.f : 1.f;

    __shared__ float4 shTop[2][16][32];   // warp w's row 6w
    __shared__ float4 shBot[2][16][32];   // warp w's row 6w+5
    const float4 z4 = make_float4(0.f, 0.f, 0.f, 0.f);

#pragma unroll
    for (int i = 0; i < 8; i++) {
        const int p = i & 1;
        shTop[p][w][l] = a0;
        shBot[p][w][l] = a5;
        __syncthreads();
        // issue halo loads early (29-cyc LDS latency hidden by middle-row work)
        float4 aT = (w > 0)  ? shBot[p][w - 1][l] : z4;
        float4 aB = (w < 15) ? shTop[p][w + 1][l] : z4;
        // pairs from OLD values (before any a_i is overwritten)
        float4 c01 = fmax4(a0, a1);
        float4 c23 = fmax4(a2, a3);
        float4 c45 = fmax4(a4, a5);
        // middle rows: register-only, fills the LDS latency window
        float4 v1 = fmax4(c01, a2);
        float4 v2 = fmax4(a1,  c23);
        float4 v3 = fmax4(c23, a4);
        float4 v4 = fmax4(a3,  c45);
        a1 = hmask(v1, m1, eL, eR);
        a2 = hmask(v2, m2, eL, eR);
        a3 = hmask(v3, m3, eL, eR);
        a4 = hmask(v4, m4, eL, eR);
        // edge rows consume the halo loads last
        float4 v0 = fmax4(aT,  c01);
        float4 v5 = fmax4(c45, aB);
        a0 = hmask(v0, m0, eL, eR);
        a5 = hmask(v5, m5, eL, eR);
    }

    // store valid (margin-8 or image-edge) region; overlap writes are identical
    const int vx0 = (X0 == 0)   ? 0   : X0 + 8;
    const int vx1 = (X0 == 384) ? 512 : X0 + 120;
    const int vy0 = (Y0 == 0)   ? 0   : Y0 + 8;
    const int vy1 = (Y0 == 416) ? 512 : Y0 + 88;
    float* obase = out + (size_t)img * IMG2;
    if (gx >= vx0 && gx < vx1) {
        if (gy0 + 0 >= vy0 && gy0 + 0 < vy1)
            *reinterpret_cast<float4*>(obase + (gy0 + 0) * IMG + gx) = a0;
        if (gy0 + 1 >= vy0 && gy0 + 1 < vy1)
            *reinterpret_cast<float4*>(obase + (gy0 + 1) * IMG + gx) = a1;
        if (gy0 + 2 >= vy0 && gy0 + 2 < vy1)
            *reinterpret_cast<float4*>(obase + (gy0 + 2) * IMG + gx) = a2;
        if (gy0 + 3 >= vy0 && gy0 + 3 < vy1)
            *reinterpret_cast<float4*>(obase + (gy0 + 3) * IMG + gx) = a3;
        if (gy0 + 4 >= vy0 && gy0 + 4 < vy1)
            *reinterpret_cast<float4*>(obase + (gy0 + 4) * IMG + gx) = a4;
        if (gy0 + 5 >= vy0 && gy0 + 5 < vy1)
            *reinterpret_cast<float4*>(obase + (gy0 + 5) * IMG + gx) = a5;
    }
}

// ---------------- uniqueness: bitmap scatter with fused count ----------------
// atomicOr's return value credits each newly-set bit to exactly one thread, so
// the separate popcount pass is eliminated.
__global__ void __launch_bounds__(256) scatter_kernel() {
    int i = blockIdx.x * blockDim.x + threadIdx.x;   // float4 index, < NTOT/4
    float4 v = reinterpret_cast<const float4*>(g_buf[1])[i];
    const int which = (i < (NTEN / 4)) ? 0 : 1;      // warp-uniform (NTEN/4 % 32 == 0)
    unsigned* bmp = g_bmp[which];
    unsigned ids[4] = {(unsigned)v.x, (unsigned)v.y, (unsigned)v.z, (unsigned)v.w};
    unsigned prev = 0xffffffffu;
    int cnt = 0;
#pragma unroll
    for (int k = 0; k < 4; k++) {
        unsigned id = ids[k];
        if (id == prev) continue;                 // spatial dedup (labels cluster)
        prev = id;
        unsigned w = id >> 5, m = 1u << (id & 31);
        if (!(bmp[w] & m)) {                      // test first: kills hot-word storms
            unsigned old = atomicOr(&bmp[w], m);
            if (!(old & m)) cnt++;                // this thread flipped the bit
        }
    }
#pragma unroll
    for (int o = 16; o; o >>= 1) cnt += __shfl_down_sync(FULLMASK, cnt, o);
    if ((threadIdx.x & 31) == 0 && cnt)
        atomicAdd(&g_cnt[which], cnt);
}

// ---------------- epilogue ----------------
__global__ void final_kernel(float* __restrict__ out) {
    float acc = 0.f;
    for (int b = 0; b < NBATCH; b++) {
        float num = 0.f, den = 0.f;
        for (int c = 0; c < 32; c++) { num += g_pnum[b * 32 + c]; den += g_pden[b * 32 + c]; }
        acc += 1.0f - (num + 1.0f) / (den + 1.0f);
    }
    float nl = (float)(g_cnt[0] - 1);   // count_unique(labels) - 1
    float nt = (float)g_cnt[1];         // count_unique(target_number)
    float pen = sqrtf(nl / nt);
    if (!isfinite(pen)) pen = (float)NBATCH;
    pen = fminf(fmaxf(pen, 1.0f), (float)NBATCH);
    out[0] = (acc / (float)NBATCH) * pen;
}

// ---------------- launch ----------------
extern "C" void kernel_launch(void* const* d_in, const int* in_sizes, int n_in,
                              void* d_out, int out_size) {
    const float* p = (const float*)d_in[0];
    const float* t = (const float*)d_in[1];
    float* out = (float*)d_out;

    init_kernel<<<512, 256>>>();

    dim3 rgrid(32, 16);
    reduce_kernel<<<rgrid, 256>>>(p, t);

    seed_kernel<<<NTEN / 4 / 256, 256>>>(p, t);

    // 25 launches x 8 fused iterations = 200; ping-pong g_buf[0] <-> g_buf[1]
    dim3 pgrid(5, 7, 32);
    for (int it = 0; it < 25; ++it)
        prop8_kernel<<<pgrid, 512>>>(it & 1);     // final result lands in g_buf[1]

    scatter_kernel<<<NTOT / 4 / 256, 256>>>();

    final_kernel<<<1, 1>>>(out);
}

// round 10
// speedup vs baseline: 1.1609x; 1.0953x over previous
#include <cuda_runtime.h>
#include <math.h>

#define IMG    512
#define IMG2   (IMG * IMG)        // 262144 elements per image
#define NBATCH 16
#define NTEN   (NBATCH * IMG2)    // 4194304 per tensor
#define NTOT   (2 * NTEN)         // 8388608 both tensors
#define BMP_WORDS 131080          // ceil((NTEN+1)/32) = 131073, padded
#define FULLMASK 0xffffffffu

// ---------------- device scratch (static, no allocation) ----------------
__device__ float    g_buf[2][NTOT];       // ping-pong label buffers (pred | target)
__device__ unsigned g_bmp[2][BMP_WORDS];  // uniqueness bitmaps
__device__ float    g_pnum[512];          // per (batch,chunk) partial sum p*t
__device__ float    g_pden[512];          // per (batch,chunk) partial sum p^2+t^2
__device__ int      g_maxbits[2];         // float-as-int global max of p, t (values >= 0)
__device__ int      g_cnt[2];             // unique counts

// ---------------- helpers ----------------
// 3-input max on nonnegative floats via DPX int max (bit order == float order
// for values >= 0). One IMNMX3-class ALU op instead of two chained FMNMX.
__device__ __forceinline__ float max3f(float a, float b, float c) {
    return __int_as_float(__vimax3_s32(__float_as_int(a),
                                       __float_as_int(b),
                                       __float_as_int(c)));
}

// ---------------- init: clear scratch ----------------
__global__ void init_kernel() {
    int i = blockIdx.x * blockDim.x + threadIdx.x;
    int stride = gridDim.x * blockDim.x;
    for (int w = i; w < BMP_WORDS; w += stride) {
        g_bmp[0][w] = 0u;
        g_bmp[1][w] = 0u;
    }
    if (i < 512) { g_pnum[i] = 0.f; g_pden[i] = 0.f; }
    if (i < 2)   { g_maxbits[i] = 0; g_cnt[i] = 0; }
}

// ---------------- pass 1: dice partial sums + global maxes ----------------
__global__ void __launch_bounds__(256) reduce_kernel(const float* __restrict__ p,
                                                     const float* __restrict__ t) {
    const int b = blockIdx.y, c = blockIdx.x, tid = threadIdx.x;
    const float4* p4 = reinterpret_cast<const float4*>(p + (size_t)b * IMG2) + c * 2048;
    const float4* t4 = reinterpret_cast<const float4*>(t + (size_t)b * IMG2) + c * 2048;
    float s1 = 0.f, s2 = 0.f, mp = 0.f, mt = 0.f;
#pragma unroll
    for (int k = 0; k < 8; k++) {
        float4 a = p4[k * 256 + tid];
        float4 d = t4[k * 256 + tid];
        s1 += a.x * d.x + a.y * d.y + a.z * d.z + a.w * d.w;
        s2 += a.x * a.x + a.y * a.y + a.z * a.z + a.w * a.w;
        s2 += d.x * d.x + d.y * d.y + d.z * d.z + d.w * d.w;
        mp = fmaxf(mp, fmaxf(fmaxf(a.x, a.y), fmaxf(a.z, a.w)));
        mt = fmaxf(mt, fmaxf(fmaxf(d.x, d.y), fmaxf(d.z, d.w)));
    }
#pragma unroll
    for (int o = 16; o; o >>= 1) {
        s1 += __shfl_down_sync(FULLMASK, s1, o);
        s2 += __shfl_down_sync(FULLMASK, s2, o);
        mp = fmaxf(mp, __shfl_down_sync(FULLMASK, mp, o));
        mt = fmaxf(mt, __shfl_down_sync(FULLMASK, mt, o));
    }
    __shared__ float sh1[8], sh2[8], shm[8], sht[8];
    if ((tid & 31) == 0) {
        int w = tid >> 5;
        sh1[w] = s1; sh2[w] = s2; shm[w] = mp; sht[w] = mt;
    }
    __syncthreads();
    if (tid == 0) {
        float a1 = sh1[0], a2 = sh2[0], m1 = shm[0], m2 = sht[0];
        for (int w = 1; w < 8; w++) {
            a1 += sh1[w]; a2 += sh2[w];
            m1 = fmaxf(m1, shm[w]); m2 = fmaxf(m2, sht[w]);
        }
        g_pnum[b * 32 + c] = a1;
        g_pden[b * 32 + c] = a2;
        atomicMax(&g_maxbits[0], __float_as_int(m1));  // vals >= 0: int order == float order
        atomicMax(&g_maxbits[1], __float_as_int(m2));
    }
}

// ---------------- pass 2: build seed arrays ----------------
__global__ void __launch_bounds__(256) seed_kernel(const float* __restrict__ p,
                                                   const float* __restrict__ t) {
    int i = blockIdx.x * blockDim.x + threadIdx.x;   // float4 index, < NTEN/4
    float thp = 0.5f * __int_as_float(g_maxbits[0]);
    float tht = 0.5f * __int_as_float(g_maxbits[1]);
    int base = 4 * i;
    float4 a = reinterpret_cast<const float4*>(p)[i];
    float4 s;
    s.x = (a.x > thp) ? (float)(base + 1) : 0.f;
    s.y = (a.y > thp) ? (float)(base + 2) : 0.f;
    s.z = (a.z > thp) ? (float)(base + 3) : 0.f;
    s.w = (a.w > thp) ? (float)(base + 4) : 0.f;
    reinterpret_cast<float4*>(g_buf[0])[i] = s;
    float4 d = reinterpret_cast<const float4*>(t)[i];
    s.x = (d.x > tht) ? (float)(base + 1) : 0.f;
    s.y = (d.y > tht) ? (float)(base + 2) : 0.f;
    s.z = (d.z > tht) ? (float)(base + 3) : 0.f;
    s.w = (d.w > tht) ? (float)(base + 4) : 0.f;
    reinterpret_cast<float4*>(g_buf[0] + NTEN)[i] = s;
}

// ---------------- fused propagation: 8 masked 3x3 max-pool iterations ----------------
// R3 geometry: register tile 128x64; valid output = tile minus margin 8 on
// image-interior sides. Warp w (0..15) owns rows 4w..4w+3; lane l owns cols
// 4l..4l+3 (float4). ALL 3-input maxes are single DPX __vimax3_s32 ops (bit
// order == float order for nonneg values): 1 ALU op per pixel per direction,
// halving both instruction count and dependency depth of the max stages.
// Invariant 0/1 masks + lane-edge clamps via FMUL (FMA pipe). Vertical halo
// via smem (selects at warp 0/15), parity double-buffered, 1 syncthreads/iter.
__device__ __forceinline__ float4 hmask(const float4 v, const float4 m,
                                        float eL, float eR) {
    float vl = __shfl_up_sync(FULLMASK,  v.w, 1) * eL;
    float vr = __shfl_down_sync(FULLMASK, v.x, 1) * eR;
    float4 o;
    o.x = max3f(vl,  v.x, v.y) * m.x;   // mask FMUL: exact for 0/1 masks
    o.y = max3f(v.x, v.y, v.z) * m.y;
    o.z = max3f(v.y, v.z, v.w) * m.z;
    o.w = max3f(v.z, v.w, vr)  * m.w;
    return o;
}
__device__ __forceinline__ float4 vmax3(const float4 a, const float4 b, const float4 c) {
    return make_float4(max3f(a.x, b.x, c.x), max3f(a.y, b.y, c.y),
                       max3f(a.z, b.z, c.z), max3f(a.w, b.w, c.w));
}
__device__ __forceinline__ float4 mk_mask(const float4 a) {
    return make_float4(a.x > 0.f ? 1.f : 0.f, a.y > 0.f ? 1.f : 0.f,
                       a.z > 0.f ? 1.f : 0.f, a.w > 0.f ? 1.f : 0.f);
}

__global__ void __launch_bounds__(512, 2) prop8_kernel(int src) {
    const float* __restrict__ in  = g_buf[src];
    float*       __restrict__ out = g_buf[src ^ 1];
    const int img = blockIdx.z;
    const int X0 = min((int)blockIdx.x * 112, 384);   // {0,112,224,336,384}
    const int Y0 = min((int)blockIdx.y * 48,  448);   // {0,48,...,432,448}
    const int w = threadIdx.x >> 5, l = threadIdx.x & 31;
    const int gx  = X0 + 4 * l;
    const int gy0 = Y0 + 4 * w;
    const float* base = in + (size_t)img * IMG2;

    float4 a0 = *reinterpret_cast<const float4*>(base + (gy0 + 0) * IMG + gx);
    float4 a1 = *reinterpret_cast<const float4*>(base + (gy0 + 1) * IMG + gx);
    float4 a2 = *reinterpret_cast<const float4*>(base + (gy0 + 2) * IMG + gx);
    float4 a3 = *reinterpret_cast<const float4*>(base + (gy0 + 3) * IMG + gx);

    // invariant 0/1 mask registers (masked-out pixels stay 0 across all iters)
    float4 m0 = mk_mask(a0), m1 = mk_mask(a1);
    float4 m2 = mk_mask(a2), m3 = mk_mask(a3);

    const float eL = (l == 0)  ? 0.f : 1.f;   // tile x-edge clamp
    const float eR = (l == 31) ? 0.f : 1.f;

    __shared__ float4 shTop[2][16][32];   // warp w's row 4w
    __shared__ float4 shBot[2][16][32];   // warp w's row 4w+3
    const float4 z4 = make_float4(0.f, 0.f, 0.f, 0.f);

#pragma unroll
    for (int i = 0; i < 8; i++) {
        const int p = i & 1;
        shTop[p][w][l] = a0;
        shBot[p][w][l] = a3;
        __syncthreads();
        float4 aT = (w > 0)  ? shBot[p][w - 1][l] : z4;
        float4 aB = (w < 15) ? shTop[p][w + 1][l] : z4;
        // vertical 3-max: one DPX op per pixel
        float4 v0 = vmax3(aT, a0, a1);
        float4 v1 = vmax3(a0, a1, a2);
        float4 v2 = vmax3(a1, a2, a3);
        float4 v3 = vmax3(a2, a3, aB);
        a0 = hmask(v0, m0, eL, eR);
        a1 = hmask(v1, m1, eL, eR);
        a2 = hmask(v2, m2, eL, eR);
        a3 = hmask(v3, m3, eL, eR);
    }

    // store valid (margin-8 or image-edge) region; overlap writes are identical
    const int vx0 = (X0 == 0)   ? 0   : X0 + 8;
    const int vx1 = (X0 == 384) ? 512 : X0 + 120;
    const int vy0 = (Y0 == 0)   ? 0   : Y0 + 8;
    const int vy1 = (Y0 == 448) ? 512 : Y0 + 56;
    float* obase = out + (size_t)img * IMG2;
    if (gx >= vx0 && gx < vx1) {
        if (gy0 + 0 >= vy0 && gy0 + 0 < vy1)
            *reinterpret_cast<float4*>(obase + (gy0 + 0) * IMG + gx) = a0;
        if (gy0 + 1 >= vy0 && gy0 + 1 < vy1)
            *reinterpret_cast<float4*>(obase + (gy0 + 1) * IMG + gx) = a1;
        if (gy0 + 2 >= vy0 && gy0 + 2 < vy1)
            *reinterpret_cast<float4*>(obase + (gy0 + 2) * IMG + gx) = a2;
        if (gy0 + 3 >= vy0 && gy0 + 3 < vy1)
            *reinterpret_cast<float4*>(obase + (gy0 + 3) * IMG + gx) = a3;
    }
}

// ---------------- uniqueness: bitmap scatter with fused count ----------------
__global__ void __launch_bounds__(256) scatter_kernel() {
    int i = blockIdx.x * blockDim.x + threadIdx.x;   // float4 index, < NTOT/4
    float4 v = reinterpret_cast<const float4*>(g_buf[1])[i];
    const int which = (i < (NTEN / 4)) ? 0 : 1;      // warp-uniform (NTEN/4 % 32 == 0)
    unsigned* bmp = g_bmp[which];
    unsigned ids[4] = {(unsigned)v.x, (unsigned)v.y, (unsigned)v.z, (unsigned)v.w};
    unsigned prev = 0xffffffffu;
    int cnt = 0;
#pragma unroll
    for (int k = 0; k < 4; k++) {
        unsigned id = ids[k];
        if (id == prev) continue;                 // spatial dedup (labels cluster)
        prev = id;
        unsigned w = id >> 5, m = 1u << (id & 31);
        if (!(bmp[w] & m)) {                      // test first: kills hot-word storms
            unsigned old = atomicOr(&bmp[w], m);
            if (!(old & m)) cnt++;                // this thread flipped the bit
        }
    }
#pragma unroll
    for (int o = 16; o; o >>= 1) cnt += __shfl_down_sync(FULLMASK, cnt, o);
    if ((threadIdx.x & 31) == 0 && cnt)
        atomicAdd(&g_cnt[which], cnt);
}

// ---------------- epilogue ----------------
__global__ void final_kernel(float* __restrict__ out) {
    float acc = 0.f;
    for (int b = 0; b < NBATCH; b++) {
        float num = 0.f, den = 0.f;
        for (int c = 0; c < 32; c++) { num += g_pnum[b * 32 + c]; den += g_pden[b * 32 + c]; }
        acc += 1.0f - (num + 1.0f) / (den + 1.0f);
    }
    float nl = (float)(g_cnt[0] - 1);   // count_unique(labels) - 1
    float nt = (float)g_cnt[1];         // count_unique(target_number)
    float pen = sqrtf(nl / nt);
    if (!isfinite(pen)) pen = (float)NBATCH;
    pen = fminf(fmaxf(pen, 1.0f), (float)NBATCH);
    out[0] = (acc / (float)NBATCH) * pen;
}

// ---------------- launch ----------------
extern "C" void kernel_launch(void* const* d_in, const int* in_sizes, int n_in,
                              void* d_out, int out_size) {
    const float* p = (const float*)d_in[0];
    const float* t = (const float*)d_in[1];
    float* out = (float*)d_out;

    init_kernel<<<512, 256>>>();

    dim3 rgrid(32, 16);
    reduce_kernel<<<rgrid, 256>>>(p, t);

    seed_kernel<<<NTEN / 4 / 256, 256>>>(p, t);

    // 25 launches x 8 fused iterations = 200; ping-pong g_buf[0] <-> g_buf[1]
    dim3 pgrid(5, 11, 32);
    for (int it = 0; it < 25; ++it)
        prop8_kernel<<<pgrid, 512>>>(it & 1);     // final result lands in g_buf[1]

    scatter_kernel<<<NTOT / 4 / 256, 256>>>();

    final_kernel<<<1, 1>>>(out);
}

// round 11
// speedup vs baseline: 1.1643x; 1.0029x over previous
#include <cuda_runtime.h>
#include <math.h>

#define IMG    512
#define IMG2   (IMG * IMG)        // 262144 elements per image
#define NBATCH 16
#define NTEN   (NBATCH * IMG2)    // 4194304 per tensor
#define NTOT   (2 * NTEN)         // 8388608 both tensors
#define BMP_WORDS 131080          // ceil((NTEN+1)/32) = 131073, padded
#define FULLMASK 0xffffffffu
#define SIGNBIT  0x80000000

// ---------------- device scratch (static, no allocation) ----------------
__device__ float    g_buf[2][NTOT];       // ping-pong label buffers (pred | target)
__device__ unsigned g_bmp[2][BMP_WORDS];  // uniqueness bitmaps
__device__ float    g_pnum[512];          // per (batch,chunk) partial sum p*t
__device__ float    g_pden[512];          // per (batch,chunk) partial sum p^2+t^2
__device__ int      g_maxbits[2];         // float-as-int global max of p, t (values >= 0)
__device__ int      g_cnt[2];             // unique counts

// ---------------- helpers ----------------
// 3-input max in signed-int domain (DPX). For active labels (positive float
// bits) int order == float order; sentinel (negative) inputs always lose.
__device__ __forceinline__ float max3f(float a, float b, float c) {
    return __int_as_float(__vimax3_s32(__float_as_int(a),
                                       __float_as_int(b),
                                       __float_as_int(c)));
}
// apply invariant mask from the old value's sign bit: one LOP3.
// active (sign 0): o = h exact;  masked (sign 1): o negative sentinel.
__device__ __forceinline__ float sgn_or(float h, float a_old) {
    return __int_as_float(__float_as_int(h) |
                          (__float_as_int(a_old) & SIGNBIT));
}

// ---------------- init: clear scratch ----------------
__global__ void init_kernel() {
    int i = blockIdx.x * blockDim.x + threadIdx.x;
    int stride = gridDim.x * blockDim.x;
    for (int w = i; w < BMP_WORDS; w += stride) {
        g_bmp[0][w] = 0u;
        g_bmp[1][w] = 0u;
    }
    if (i < 512) { g_pnum[i] = 0.f; g_pden[i] = 0.f; }
    if (i < 2)   { g_maxbits[i] = 0; g_cnt[i] = 0; }
}

// ---------------- pass 1: dice partial sums + global maxes ----------------
__global__ void __launch_bounds__(256) reduce_kernel(const float* __restrict__ p,
                                                     const float* __restrict__ t) {
    const int b = blockIdx.y, c = blockIdx.x, tid = threadIdx.x;
    const float4* p4 = reinterpret_cast<const float4*>(p + (size_t)b * IMG2) + c * 2048;
    const float4* t4 = reinterpret_cast<const float4*>(t + (size_t)b * IMG2) + c * 2048;
    float s1 = 0.f, s2 = 0.f, mp = 0.f, mt = 0.f;
#pragma unroll
    for (int k = 0; k < 8; k++) {
        float4 a = p4[k * 256 + tid];
        float4 d = t4[k * 256 + tid];
        s1 += a.x * d.x + a.y * d.y + a.z * d.z + a.w * d.w;
        s2 += a.x * a.x + a.y * a.y + a.z * a.z + a.w * a.w;
        s2 += d.x * d.x + d.y * d.y + d.z * d.z + d.w * d.w;
        mp = fmaxf(mp, fmaxf(fmaxf(a.x, a.y), fmaxf(a.z, a.w)));
        mt = fmaxf(mt, fmaxf(fmaxf(d.x, d.y), fmaxf(d.z, d.w)));
    }
#pragma unroll
    for (int o = 16; o; o >>= 1) {
        s1 += __shfl_down_sync(FULLMASK, s1, o);
        s2 += __shfl_down_sync(FULLMASK, s2, o);
        mp = fmaxf(mp, __shfl_down_sync(FULLMASK, mp, o));
        mt = fmaxf(mt, __shfl_down_sync(FULLMASK, mt, o));
    }
    __shared__ float sh1[8], sh2[8], shm[8], sht[8];
    if ((tid & 31) == 0) {
        int w = tid >> 5;
        sh1[w] = s1; sh2[w] = s2; shm[w] = mp; sht[w] = mt;
    }
    __syncthreads();
    if (tid == 0) {
        float a1 = sh1[0], a2 = sh2[0], m1 = shm[0], m2 = sht[0];
        for (int w = 1; w < 8; w++) {
            a1 += sh1[w]; a2 += sh2[w];
            m1 = fmaxf(m1, shm[w]); m2 = fmaxf(m2, sht[w]);
        }
        g_pnum[b * 32 + c] = a1;
        g_pden[b * 32 + c] = a2;
        atomicMax(&g_maxbits[0], __float_as_int(m1));  // vals >= 0: int order == float order
        atomicMax(&g_maxbits[1], __float_as_int(m2));
    }
}

// ---------------- pass 2: build seed arrays ----------------
// active: label idx+1 (exact fp32); masked: -0.0f sentinel (sign bit = mask)
__global__ void __launch_bounds__(256) seed_kernel(const float* __restrict__ p,
                                                   const float* __restrict__ t) {
    int i = blockIdx.x * blockDim.x + threadIdx.x;   // float4 index, < NTEN/4
    float thp = 0.5f * __int_as_float(g_maxbits[0]);
    float tht = 0.5f * __int_as_float(g_maxbits[1]);
    const float neg0 = __int_as_float(SIGNBIT);
    int base = 4 * i;
    float4 a = reinterpret_cast<const float4*>(p)[i];
    float4 s;
    s.x = (a.x > thp) ? (float)(base + 1) : neg0;
    s.y = (a.y > thp) ? (float)(base + 2) : neg0;
    s.z = (a.z > thp) ? (float)(base + 3) : neg0;
    s.w = (a.w > thp) ? (float)(base + 4) : neg0;
    reinterpret_cast<float4*>(g_buf[0])[i] = s;
    float4 d = reinterpret_cast<const float4*>(t)[i];
    s.x = (d.x > tht) ? (float)(base + 1) : neg0;
    s.y = (d.y > tht) ? (float)(base + 2) : neg0;
    s.z = (d.z > tht) ? (float)(base + 3) : neg0;
    s.w = (d.w > tht) ? (float)(base + 4) : neg0;
    reinterpret_cast<float4*>(g_buf[0] + NTEN)[i] = s;
}

// ---------------- fused propagation: 8 masked 3x3 max-pool iterations ----------------
// Register tile 128x96; warp w (0..15) owns rows 6w..6w+5; lane l owns cols
// 4l..4l+3 (float4). Sentinel representation: masked cells are negative floats
// (sign invariant). Pooling max is DPX signed-int max3 (sentinels always lose
// to active labels; active results bit-exact). Mask application = one LOP3
// (h | (a_old & signbit)) — NO mask registers. Lane-edge clamps via FMUL by
// 0/1 on the FMA pipe (x0 -> +-0, neutral). Vertical halo via smem (selects
// at warp 0/15), parity double-buffered, 1 syncthreads/iter.
__device__ __forceinline__ float4 hrow(const float4 v, const float4 aold,
                                       float eL, float eR) {
    float vl = __shfl_up_sync(FULLMASK,  v.w, 1) * eL;
    float vr = __shfl_down_sync(FULLMASK, v.x, 1) * eR;
    float4 o;
    o.x = sgn_or(max3f(vl,  v.x, v.y), aold.x);
    o.y = sgn_or(max3f(v.x, v.y, v.z), aold.y);
    o.z = sgn_or(max3f(v.y, v.z, v.w), aold.z);
    o.w = sgn_or(max3f(v.z, v.w, vr),  aold.w);
    return o;
}
__device__ __forceinline__ float4 vmax3(const float4 a, const float4 b, const float4 c) {
    return make_float4(max3f(a.x, b.x, c.x), max3f(a.y, b.y, c.y),
                       max3f(a.z, b.z, c.z), max3f(a.w, b.w, c.w));
}

__global__ void __launch_bounds__(512, 2) prop8_kernel(int src) {
    const float* __restrict__ in  = g_buf[src];
    float*       __restrict__ out = g_buf[src ^ 1];
    const int img = blockIdx.z;
    const int X0 = min((int)blockIdx.x * 112, 384);   // 5 x-tiles
    const int Y0 = min((int)blockIdx.y * 80,  416);   // 7 y-tiles {0,80,...,400,416}
    const int w = threadIdx.x >> 5, l = threadIdx.x & 31;
    const int gx  = X0 + 4 * l;
    const int gy0 = Y0 + 6 * w;
    const float* base = in + (size_t)img * IMG2;

    float4 a0 = *reinterpret_cast<const float4*>(base + (gy0 + 0) * IMG + gx);
    float4 a1 = *reinterpret_cast<const float4*>(base + (gy0 + 1) * IMG + gx);
    float4 a2 = *reinterpret_cast<const float4*>(base + (gy0 + 2) * IMG + gx);
    float4 a3 = *reinterpret_cast<const float4*>(base + (gy0 + 3) * IMG + gx);
    float4 a4 = *reinterpret_cast<const float4*>(base + (gy0 + 4) * IMG + gx);
    float4 a5 = *reinterpret_cast<const float4*>(base + (gy0 + 5) * IMG + gx);

    const float eL = (l == 0)  ? 0.f : 1.f;   // tile x-edge clamp
    const float eR = (l == 31) ? 0.f : 1.f;

    __shared__ float4 shTop[2][16][32];   // warp w's row 6w
    __shared__ float4 shBot[2][16][32];   // warp w's row 6w+5
    const float4 s4 = make_float4(__int_as_float(SIGNBIT), __int_as_float(SIGNBIT),
                                  __int_as_float(SIGNBIT), __int_as_float(SIGNBIT));

#pragma unroll
    for (int i = 0; i < 8; i++) {
        const int p = i & 1;
        shTop[p][w][l] = a0;
        shBot[p][w][l] = a5;
        __syncthreads();
        float4 aT = (w > 0)  ? shBot[p][w - 1][l] : s4;   // INT_MIN sentinel: neutral
        float4 aB = (w < 15) ? shTop[p][w + 1][l] : s4;
        // vertical 3-max: one DPX op per pixel (inputs are OLD values)
        float4 v0 = vmax3(aT, a0, a1);
        float4 v1 = vmax3(a0, a1, a2);
        float4 v2 = vmax3(a1, a2, a3);
        float4 v3 = vmax3(a2, a3, a4);
        float4 v4 = vmax3(a3, a4, a5);
        float4 v5 = vmax3(a4, a5, aB);
        // horizontal 3-max + sign-propagated mask (sign never changes, so
        // using a_i after overwrite order is still safe; v's already captured)
        a0 = hrow(v0, a0, eL, eR);
        a1 = hrow(v1, a1, eL, eR);
        a2 = hrow(v2, a2, eL, eR);
        a3 = hrow(v3, a3, eL, eR);
        a4 = hrow(v4, a4, eL, eR);
        a5 = hrow(v5, a5, eL, eR);
    }

    // store valid (margin-8 or image-edge) region; overlap writes are identical
    const int vx0 = (X0 == 0)   ? 0   : X0 + 8;
    const int vx1 = (X0 == 384) ? 512 : X0 + 120;
    const int vy0 = (Y0 == 0)   ? 0   : Y0 + 8;
    const int vy1 = (Y0 == 416) ? 512 : Y0 + 88;
    float* obase = out + (size_t)img * IMG2;
    if (gx >= vx0 && gx < vx1) {
        if (gy0 + 0 >= vy0 && gy0 + 0 < vy1)
            *reinterpret_cast<float4*>(obase + (gy0 + 0) * IMG + gx) = a0;
        if (gy0 + 1 >= vy0 && gy0 + 1 < vy1)
            *reinterpret_cast<float4*>(obase + (gy0 + 1) * IMG + gx) = a1;
        if (gy0 + 2 >= vy0 && gy0 + 2 < vy1)
            *reinterpret_cast<float4*>(obase + (gy0 + 2) * IMG + gx) = a2;
        if (gy0 + 3 >= vy0 && gy0 + 3 < vy1)
            *reinterpret_cast<float4*>(obase + (gy0 + 3) * IMG + gx) = a3;
        if (gy0 + 4 >= vy0 && gy0 + 4 < vy1)
            *reinterpret_cast<float4*>(obase + (gy0 + 4) * IMG + gx) = a4;
        if (gy0 + 5 >= vy0 && gy0 + 5 < vy1)
            *reinterpret_cast<float4*>(obase + (gy0 + 5) * IMG + gx) = a5;
    }
}

// ---------------- uniqueness: bitmap scatter with fused count ----------------
// Sentinels (negative) clamp to 0 = background, exactly the reference's 0 label.
__global__ void __launch_bounds__(256) scatter_kernel() {
    int i = blockIdx.x * blockDim.x + threadIdx.x;   // float4 index, < NTOT/4
    float4 v = reinterpret_cast<const float4*>(g_buf[1])[i];
    const int which = (i < (NTEN / 4)) ? 0 : 1;      // warp-uniform (NTEN/4 % 32 == 0)
    unsigned* bmp = g_bmp[which];
    unsigned ids[4] = {(unsigned)fmaxf(v.x, 0.f), (unsigned)fmaxf(v.y, 0.f),
                       (unsigned)fmaxf(v.z, 0.f), (unsigned)fmaxf(v.w, 0.f)};
    unsigned prev = 0xffffffffu;
    int cnt = 0;
#pragma unroll
    for (int k = 0; k < 4; k++) {
        unsigned id = ids[k];
        if (id == prev) continue;                 // spatial dedup (labels cluster)
        prev = id;
        unsigned w = id >> 5, m = 1u << (id & 31);
        if (!(bmp[w] & m)) {                      // test first: kills hot-word storms
            unsigned old = atomicOr(&bmp[w], m);
            if (!(old & m)) cnt++;                // this thread flipped the bit
        }
    }
#pragma unroll
    for (int o = 16; o; o >>= 1) cnt += __shfl_down_sync(FULLMASK, cnt, o);
    if ((threadIdx.x & 31) == 0 && cnt)
        atomicAdd(&g_cnt[which], cnt);
}

// ---------------- epilogue ----------------
__global__ void final_kernel(float* __restrict__ out) {
    float acc = 0.f;
    for (int b = 0; b < NBATCH; b++) {
        float num = 0.f, den = 0.f;
        for (int c = 0; c < 32; c++) { num += g_pnum[b * 32 + c]; den += g_pden[b * 32 + c]; }
        acc += 1.0f - (num + 1.0f) / (den + 1.0f);
    }
    float nl = (float)(g_cnt[0] - 1);   // count_unique(labels) - 1
    float nt = (float)g_cnt[1];         // count_unique(target_number)
    float pen = sqrtf(nl / nt);
    if (!isfinite(pen)) pen = (float)NBATCH;
    pen = fminf(fmaxf(pen, 1.0f), (float)NBATCH);
    out[0] = (acc / (float)NBATCH) * pen;
}

// ---------------- launch ----------------
extern "C" void kernel_launch(void* const* d_in, const int* in_sizes, int n_in,
                              void* d_out, int out_size) {
    const float* p = (const float*)d_in[0];
    const float* t = (const float*)d_in[1];
    float* out = (float*)d_out;

    init_kernel<<<512, 256>>>();

    dim3 rgrid(32, 16);
    reduce_kernel<<<rgrid, 256>>>(p, t);

    seed_kernel<<<NTEN / 4 / 256, 256>>>(p, t);

    // 25 launches x 8 fused iterations = 200; ping-pong g_buf[0] <-> g_buf[1]
    dim3 pgrid(5, 7, 32);
    for (int it = 0; it < 25; ++it)
        prop8_kernel<<<pgrid, 512>>>(it & 1);     // final result lands in g_buf[1]

    scatter_kernel<<<NTOT / 4 / 256, 256>>>();

    final_kernel<<<1, 1>>>(out);
}